// round 8
// baseline (speedup 1.0000x reference)
#include <cuda_runtime.h>
#include <cuda_bf16.h>
#include <cstdint>

// Shapes
#define B_DIM 2048
#define N_Z 8
#define NOISE 32
#define STATE 1024
#define HID 1024
#define EPI_H 512
#define PRIOR_H 5
#define PRI_N 160   // 32 ensembles * 5
#define KTOT 2048   // xf concat length

typedef unsigned long long u64;

// ---- f32x2 helpers (prior gemm) ----
__device__ __forceinline__ u64 pk2(float lo, float hi) {
    u64 r; asm("mov.b64 %0,{%1,%2};" : "=l"(r) : "f"(lo), "f"(hi)); return r;
}
__device__ __forceinline__ u64 fma2(u64 a, u64 b, u64 c) {
    u64 d; asm("fma.rn.f32x2 %0,%1,%2,%3;" : "=l"(d) : "l"(a), "l"(b), "l"(c)); return d;
}
__device__ __forceinline__ float2 unpk(u64 v) {
    float2 r; asm("mov.b64 {%0,%1},%2;" : "=f"(r.x), "=f"(r.y) : "l"(v)); return r;
}

__device__ __forceinline__ uint32_t smem_u32(const void* p) {
    uint32_t a;
    asm("{ .reg .u64 t; cvta.to.shared.u64 t, %1; cvt.u32.u64 %0, t; }" : "=r"(a) : "l"(p));
    return a;
}

// ---- Scratch (no allocation allowed) ----
__device__ float g_H[B_DIM * EPI_H];
__device__ float g_P1[B_DIM * PRI_N];
__device__ float g_W1r[STATE * PRI_N];
__device__ __align__(16) __nv_bfloat16 g_Ahi[B_DIM * KTOT];   // 8 MB
__device__ __align__(16) __nv_bfloat16 g_Alo[B_DIM * KTOT];   // 8 MB
__device__ __align__(16) __nv_bfloat16 g_Bhi[EPI_H * KTOT];   // 2 MB, [n][k]
__device__ __align__(16) __nv_bfloat16 g_Blo[EPI_H * KTOT];   // 2 MB

// ---------------------------------------------------------------------------
// Prep: split A = [x|feature] into bf16 hi/lo, row-major [2048][2048]
// ---------------------------------------------------------------------------
__global__ __launch_bounds__(256) void convert_split_A(
    const float* __restrict__ X, const float* __restrict__ F) {
    int i4 = blockIdx.x * 256 + threadIdx.x;
    int row = i4 >> 9;
    int c4 = i4 & 511;
    const float* src = (c4 < 256) ? (X + row * 1024 + c4 * 4)
                                  : (F + row * 1024 + (c4 - 256) * 4);
    float4 v = *(const float4*)src;
    __nv_bfloat16 h0 = __float2bfloat16_rn(v.x), h1 = __float2bfloat16_rn(v.y);
    __nv_bfloat16 h2 = __float2bfloat16_rn(v.z), h3 = __float2bfloat16_rn(v.w);
    __nv_bfloat16 l0 = __float2bfloat16_rn(v.x - __bfloat162float(h0));
    __nv_bfloat16 l1 = __float2bfloat16_rn(v.y - __bfloat162float(h1));
    __nv_bfloat16 l2 = __float2bfloat16_rn(v.z - __bfloat162float(h2));
    __nv_bfloat16 l3 = __float2bfloat16_rn(v.w - __bfloat162float(h3));
    __nv_bfloat162 ph0 = __halves2bfloat162(h0, h1), ph1 = __halves2bfloat162(h2, h3);
    __nv_bfloat162 pl0 = __halves2bfloat162(l0, l1), pl1 = __halves2bfloat162(l2, l3);
    uint2 uh; uh.x = *(uint32_t*)&ph0; uh.y = *(uint32_t*)&ph1;
    uint2 ul; ul.x = *(uint32_t*)&pl0; ul.y = *(uint32_t*)&pl1;
    size_t off = (size_t)row * KTOT + c4 * 4;
    *(uint2*)(g_Ahi + off) = uh;
    *(uint2*)(g_Alo + off) = ul;
}

// ---------------------------------------------------------------------------
// Prep: transpose+split W[0:2048][512] -> Bhi/Blo [512][2048]
// ---------------------------------------------------------------------------
__global__ __launch_bounds__(256) void transpose_split_W(const float* __restrict__ W) {
    __shared__ float t[32][33];
    int kt = blockIdx.x;   // 64
    int nt = blockIdx.y;   // 16
    int tx = threadIdx.x;  // 32
    int ty = threadIdx.y;  // 8
#pragma unroll
    for (int i = 0; i < 4; i++)
        t[ty * 4 + i][tx] = W[(size_t)(kt * 32 + ty * 4 + i) * EPI_H + nt * 32 + tx];
    __syncthreads();
#pragma unroll
    for (int i = 0; i < 4; i++) {
        int n = nt * 32 + ty * 4 + i;
        int k = kt * 32 + tx;
        float v = t[tx][ty * 4 + i];
        __nv_bfloat16 h = __float2bfloat16_rn(v);
        __nv_bfloat16 l = __float2bfloat16_rn(v - __bfloat162float(h));
        g_Bhi[(size_t)n * KTOT + k] = h;
        g_Blo[(size_t)n * KTOT + k] = l;
    }
}

// ---------------------------------------------------------------------------
// Repack Wp1[32][1024][5] -> W1r[1024][160]
// ---------------------------------------------------------------------------
__global__ void repack_wp1(const float* __restrict__ Wp1) {
    int idx = blockIdx.x * 256 + threadIdx.x;
    if (idx < STATE * PRI_N) {
        int k = idx / PRI_N;
        int c = idx - k * PRI_N;
        int e = c / PRIOR_H;
        int h = c - e * PRIOR_H;
        g_W1r[idx] = Wp1[e * (STATE * PRIOR_H) + k * PRIOR_H + h];
    }
}

// ---------------------------------------------------------------------------
// Tensor-core GEMM (bf16 3-pass hi/lo split), mma.sync m16n8k16.
// BM=64 BN=64 BK=64, 256 threads (8 warps, warp tile 32x16), 2 CTAs/SM,
// conflict-free swizzle (c ^ (r&7) over 128B rows), double buffer.
// ---------------------------------------------------------------------------
#define GM_BM 64
#define GM_BN 64
#define GM_BK 64
#define NKB (KTOT / GM_BK)    // 32
// per-buffer layout (bytes): Ahi 8K | Alo 8K | Bhi 8K | Blo 8K
#define SM_AHI 0
#define SM_ALO 8192
#define SM_BHI 16384
#define SM_BLO 24576
#define BUF_STRIDE 32768      // 32 KB, x2 = 64 KB

__device__ __forceinline__ void sts16s(uint32_t base, int r, int c, uint4 v) {
    uint32_t addr = base + r * 128 + ((c ^ (r & 7)) * 16);
    asm volatile("st.shared.v4.b32 [%0], {%1,%2,%3,%4};"
        :: "r"(addr), "r"(v.x), "r"(v.y), "r"(v.z), "r"(v.w));
}
__device__ __forceinline__ void ldmx4(uint32_t addr, uint32_t* r) {
    asm volatile("ldmatrix.sync.aligned.m8n8.x4.shared.b16 {%0,%1,%2,%3}, [%4];"
        : "=r"(r[0]), "=r"(r[1]), "=r"(r[2]), "=r"(r[3]) : "r"(addr));
}
__device__ __forceinline__ void mma16816(float* c, const uint32_t* a,
                                         uint32_t b0, uint32_t b1) {
    asm volatile("mma.sync.aligned.m16n8k16.row.col.f32.bf16.bf16.f32 "
        "{%0,%1,%2,%3},{%4,%5,%6,%7},{%8,%9},{%0,%1,%2,%3};"
        : "+f"(c[0]), "+f"(c[1]), "+f"(c[2]), "+f"(c[3])
        : "r"(a[0]), "r"(a[1]), "r"(a[2]), "r"(a[3]), "r"(b0), "r"(b1));
}

__global__ __launch_bounds__(256, 2) void gemm_mma(const float* __restrict__ bias) {
    extern __shared__ char smem_raw[];
    const uint32_t sb = smem_u32(smem_raw);

    const int tid = threadIdx.x;
    const int lane = tid & 31;
    const int wid = tid >> 5;
    const int wm = wid & 1;        // 2 m-warps x 32 rows
    const int wn = wid >> 1;       // 4 n-warps x 16 cols
    const int row0 = blockIdx.y * GM_BM;
    const int col0 = blockIdx.x * GM_BN;

    // loader: 2 chunks (16B) per thread per tensor; ch -> (r, c)
    const int r0 = tid >> 3, c0 = tid & 7;            // ch = tid
    const int r1 = (tid + 256) >> 3, c1 = tid & 7;    // ch = tid+256

    float acc[2][2][4];
#pragma unroll
    for (int mi = 0; mi < 2; mi++)
#pragma unroll
        for (int nf = 0; nf < 2; nf++)
#pragma unroll
            for (int q = 0; q < 4; q++) acc[mi][nf][q] = 0.f;

    // ---- prefetch kb=0 into buf 0 ----
    sts16s(sb + SM_AHI, r0, c0, *(const uint4*)(g_Ahi + (row0 + r0) * KTOT + c0 * 8));
    sts16s(sb + SM_AHI, r1, c1, *(const uint4*)(g_Ahi + (row0 + r1) * KTOT + c1 * 8));
    sts16s(sb + SM_ALO, r0, c0, *(const uint4*)(g_Alo + (row0 + r0) * KTOT + c0 * 8));
    sts16s(sb + SM_ALO, r1, c1, *(const uint4*)(g_Alo + (row0 + r1) * KTOT + c1 * 8));
    sts16s(sb + SM_BHI, r0, c0, *(const uint4*)(g_Bhi + (col0 + r0) * KTOT + c0 * 8));
    sts16s(sb + SM_BHI, r1, c1, *(const uint4*)(g_Bhi + (col0 + r1) * KTOT + c1 * 8));
    sts16s(sb + SM_BLO, r0, c0, *(const uint4*)(g_Blo + (col0 + r0) * KTOT + c0 * 8));
    sts16s(sb + SM_BLO, r1, c1, *(const uint4*)(g_Blo + (col0 + r1) * KTOT + c1 * 8));
    __syncthreads();

    for (int kb = 0; kb < NKB; kb++) {
        const int cur = kb & 1;
        const uint32_t bufb = sb + cur * BUF_STRIDE;

        uint4 f[8];
        if (kb + 1 < NKB) {
            int ko = (kb + 1) * GM_BK;
            f[0] = *(const uint4*)(g_Ahi + (row0 + r0) * KTOT + ko + c0 * 8);
            f[1] = *(const uint4*)(g_Ahi + (row0 + r1) * KTOT + ko + c1 * 8);
            f[2] = *(const uint4*)(g_Alo + (row0 + r0) * KTOT + ko + c0 * 8);
            f[3] = *(const uint4*)(g_Alo + (row0 + r1) * KTOT + ko + c1 * 8);
            f[4] = *(const uint4*)(g_Bhi + (col0 + r0) * KTOT + ko + c0 * 8);
            f[5] = *(const uint4*)(g_Bhi + (col0 + r1) * KTOT + ko + c1 * 8);
            f[6] = *(const uint4*)(g_Blo + (col0 + r0) * KTOT + ko + c0 * 8);
            f[7] = *(const uint4*)(g_Blo + (col0 + r1) * KTOT + ko + c1 * 8);
        }

        // ---- compute on cur buffer: 4 kblk of k16 ----
        const int lrow = lane & 15;
#pragma unroll
        for (int kblk = 0; kblk < 4; kblk++) {
            const int ch = kblk * 2 + (lane >> 4);
            uint32_t ah[2][4], al[2][4], bh[4], bl[4];
#pragma unroll
            for (int mi = 0; mi < 2; mi++) {
                int r = wm * 32 + mi * 16 + lrow;
                uint32_t off = r * 128 + ((ch ^ (r & 7)) * 16);
                ldmx4(bufb + SM_AHI + off, ah[mi]);
                ldmx4(bufb + SM_ALO + off, al[mi]);
            }
            {
                int r = wn * 16 + lrow;
                uint32_t off = r * 128 + ((ch ^ (r & 7)) * 16);
                ldmx4(bufb + SM_BHI + off, bh);
                ldmx4(bufb + SM_BLO + off, bl);
            }
#pragma unroll
            for (int mi = 0; mi < 2; mi++)
#pragma unroll
                for (int nf = 0; nf < 2; nf++) {
                    mma16816(acc[mi][nf], ah[mi], bh[nf], bh[nf + 2]);
                    mma16816(acc[mi][nf], ah[mi], bl[nf], bl[nf + 2]);
                    mma16816(acc[mi][nf], al[mi], bh[nf], bh[nf + 2]);
                }
        }

        if (kb + 1 < NKB) {
            const uint32_t nb = sb + (cur ^ 1) * BUF_STRIDE;
            sts16s(nb + SM_AHI, r0, c0, f[0]);
            sts16s(nb + SM_AHI, r1, c1, f[1]);
            sts16s(nb + SM_ALO, r0, c0, f[2]);
            sts16s(nb + SM_ALO, r1, c1, f[3]);
            sts16s(nb + SM_BHI, r0, c0, f[4]);
            sts16s(nb + SM_BHI, r1, c1, f[5]);
            sts16s(nb + SM_BLO, r0, c0, f[6]);
            sts16s(nb + SM_BLO, r1, c1, f[7]);
        }
        __syncthreads();
    }

    // ---- epilogue: add bias, store to g_H ----
#pragma unroll
    for (int mi = 0; mi < 2; mi++)
#pragma unroll
        for (int nf = 0; nf < 2; nf++) {
            int r = row0 + wm * 32 + mi * 16 + (lane >> 2);
            int cc = col0 + wn * 16 + nf * 8 + (lane & 3) * 2;
            float2 b2 = *(const float2*)(bias + cc);
            float2 v0, v1;
            v0.x = acc[mi][nf][0] + b2.x; v0.y = acc[mi][nf][1] + b2.y;
            v1.x = acc[mi][nf][2] + b2.x; v1.y = acc[mi][nf][3] + b2.y;
            *(float2*)(g_H + r * EPI_H + cc) = v0;
            *(float2*)(g_H + (r + 8) * EPI_H + cc) = v1;
        }
}

// ---------------------------------------------------------------------------
// Prior GEMM: g_P1[2048][160] = relu(x @ g_W1r + bp1)   (f32x2)
// ---------------------------------------------------------------------------
#define P_BM 64
#define P_BN 32
#define P_BK 16
__global__ __launch_bounds__(128) void sgemm_prior(
    const float* __restrict__ X, const float* __restrict__ bp1) {
    __shared__ float As[2][P_BK][P_BM + 4];
    __shared__ float Bs[2][P_BK][P_BN];

    const int tid = threadIdx.x;
    const int row0 = blockIdx.y * P_BM;
    const int col0 = blockIdx.x * P_BN;

    const int ar = tid >> 2;
    const int ac4 = tid & 3;
    const int bkr = tid >> 3;
    const int bjc = tid & 7;
    const int ty = tid >> 3;
    const int tx = tid & 7;

    u64 acc2[2][4];
#pragma unroll
    for (int i = 0; i < 2; i++)
#pragma unroll
        for (int j = 0; j < 4; j++) acc2[i][j] = 0ULL;

    float4 pa0, pa1, pb;
    {
        int k = ac4 * 4;
        pa0 = *(const float4*)(X + (row0 + ar) * STATE + k);
        pa1 = *(const float4*)(X + (row0 + ar + 32) * STATE + k);
        pb  = *(const float4*)(g_W1r + bkr * PRI_N + col0 + bjc * 4);
    }
    {
        As[0][ac4 * 4 + 0][ar] = pa0.x; As[0][ac4 * 4 + 1][ar] = pa0.y;
        As[0][ac4 * 4 + 2][ar] = pa0.z; As[0][ac4 * 4 + 3][ar] = pa0.w;
        As[0][ac4 * 4 + 0][ar + 32] = pa1.x; As[0][ac4 * 4 + 1][ar + 32] = pa1.y;
        As[0][ac4 * 4 + 2][ar + 32] = pa1.z; As[0][ac4 * 4 + 3][ar + 32] = pa1.w;
        *(float4*)&Bs[0][bkr][bjc * 4] = pb;
    }
    __syncthreads();

    const int NT = STATE / P_BK;
    int buf = 0;
    for (int kt = 0; kt < NT; kt++) {
        if (kt + 1 < NT) {
            int kg = (kt + 1) * P_BK + ac4 * 4;
            pa0 = *(const float4*)(X + (row0 + ar) * STATE + kg);
            pa1 = *(const float4*)(X + (row0 + ar + 32) * STATE + kg);
            pb  = *(const float4*)(g_W1r + ((kt + 1) * P_BK + bkr) * PRI_N + col0 + bjc * 4);
        }
#pragma unroll
        for (int kk = 0; kk < P_BK; kk++) {
            ulonglong2 aa = *(const ulonglong2*)&As[buf][kk][ty * 4];
            float4 rb = *(const float4*)&Bs[buf][kk][tx * 4];
            u64 a2[2] = {aa.x, aa.y};
            u64 bd[4];
            bd[0] = pk2(rb.x, rb.x); bd[1] = pk2(rb.y, rb.y);
            bd[2] = pk2(rb.z, rb.z); bd[3] = pk2(rb.w, rb.w);
#pragma unroll
            for (int i = 0; i < 2; i++)
#pragma unroll
                for (int j = 0; j < 4; j++)
                    acc2[i][j] = fma2(a2[i], bd[j], acc2[i][j]);
        }
        if (kt + 1 < NT) {
            int nb = buf ^ 1;
            As[nb][ac4 * 4 + 0][ar] = pa0.x; As[nb][ac4 * 4 + 1][ar] = pa0.y;
            As[nb][ac4 * 4 + 2][ar] = pa0.z; As[nb][ac4 * 4 + 3][ar] = pa0.w;
            As[nb][ac4 * 4 + 0][ar + 32] = pa1.x; As[nb][ac4 * 4 + 1][ar + 32] = pa1.y;
            As[nb][ac4 * 4 + 2][ar + 32] = pa1.z; As[nb][ac4 * 4 + 3][ar + 32] = pa1.w;
            *(float4*)&Bs[nb][bkr][bjc * 4] = pb;
        }
        __syncthreads();
        buf ^= 1;
    }

    float4 bv = *(const float4*)(bp1 + col0 + tx * 4);
#pragma unroll
    for (int i2 = 0; i2 < 2; i2++) {
        float2 u0 = unpk(acc2[i2][0]), u1 = unpk(acc2[i2][1]);
        float2 u2 = unpk(acc2[i2][2]), u3 = unpk(acc2[i2][3]);
        int r = row0 + ty * 4 + 2 * i2;
        float4 olo, ohi;
        olo.x = fmaxf(u0.x + bv.x, 0.f); olo.y = fmaxf(u1.x + bv.y, 0.f);
        olo.z = fmaxf(u2.x + bv.z, 0.f); olo.w = fmaxf(u3.x + bv.w, 0.f);
        ohi.x = fmaxf(u0.y + bv.x, 0.f); ohi.y = fmaxf(u1.y + bv.y, 0.f);
        ohi.z = fmaxf(u2.y + bv.z, 0.f); ohi.w = fmaxf(u3.y + bv.w, 0.f);
        *(float4*)(g_P1 + r * PRI_N + col0 + tx * 4) = olo;
        *(float4*)(g_P1 + (r + 1) * PRI_N + col0 + tx * 4) = ohi;
    }
}

// ---------------------------------------------------------------------------
// Fused epilogue: preload Z + priors + Hj for all 8 b upfront, double-buffered
// reduction -> 1 syncthreads per b.
// ---------------------------------------------------------------------------
__global__ __launch_bounds__(512, 1) void epilogue_kernel(
    const float* __restrict__ Z, const float* __restrict__ Wep1,
    const float* __restrict__ Wep2, const float* __restrict__ bep2,
    const float* __restrict__ Wp2, const float* __restrict__ bp2,
    const float* __restrict__ Wp3, const float* __restrict__ bp3,
    float* __restrict__ out) {
    __shared__ __align__(16) float sZ8[8 * N_Z * NOISE];  // 8 KB
    __shared__ float sP8[8][NOISE];                       // 1 KB
    __shared__ float sRed[2][16][N_Z];

    const int tid = threadIdx.x;
    const int j = tid;
    const int lane = tid & 31;
    const int warp = tid >> 5;
    const int b0 = blockIdx.x * 8;

    // register-resident weight slices
    float w1z[NOISE];
    float w2t[NOISE];
#pragma unroll
    for (int k = 0; k < NOISE; k++)
        w1z[k] = Wep1[(2048 + k) * EPI_H + j];
#pragma unroll
    for (int k4 = 0; k4 < NOISE / 4; k4++) {
        float4 v = *(const float4*)(Wep2 + j * NOISE + k4 * 4);
        w2t[k4 * 4 + 0] = v.x; w2t[k4 * 4 + 1] = v.y;
        w2t[k4 * 4 + 2] = v.z; w2t[k4 * 4 + 3] = v.w;
    }

    // prefetch Hj for all 8 b
    float Hj[8];
#pragma unroll
    for (int q = 0; q < 8; q++)
        Hj[q] = g_H[(b0 + q) * EPI_H + j];

    // upfront loads: warps 8-15 load Z (8 b contiguous), warps 0-7 do priors
    if (tid >= 256) {
        int t = tid - 256;
        const float* zsrc = Z + b0 * (N_Z * NOISE);
#pragma unroll
        for (int q = 0; q < 8; q++)
            sZ8[q * 256 + t] = zsrc[q * 256 + t];
    } else {
        int bq = tid >> 5;          // 0..7
        int e = tid & 31;
        const float* p1 = g_P1 + (b0 + bq) * PRI_N + e * PRIOR_H;
        float h1[PRIOR_H];
#pragma unroll
        for (int h = 0; h < PRIOR_H; h++) h1[h] = p1[h];
        float h2[PRIOR_H];
#pragma unroll
        for (int g = 0; g < PRIOR_H; g++) {
            float s = bp2[e * PRIOR_H + g];
#pragma unroll
            for (int h = 0; h < PRIOR_H; h++)
                s = fmaf(h1[h], Wp2[e * 25 + h * PRIOR_H + g], s);
            h2[g] = fmaxf(s, 0.f);
        }
        float p = bp3[e];
#pragma unroll
        for (int g = 0; g < PRIOR_H; g++)
            p = fmaf(h2[g], Wp3[e * PRIOR_H + g], p);
        sP8[bq][e] = p + bep2[e];
    }
    __syncthreads();

    for (int bi = 0; bi < 8; bi++) {
        const float* zb = sZ8 + bi * (N_Z * NOISE);
        float part[N_Z];
#pragma unroll
        for (int n = 0; n < N_Z; n++) {
            float hz = 0.f, wz = 0.f;
            const float4* z4 = (const float4*)(zb + n * NOISE);
#pragma unroll
            for (int k4 = 0; k4 < NOISE / 4; k4++) {
                float4 zv = z4[k4];
                int k = k4 * 4;
                hz = fmaf(zv.x, w1z[k + 0], hz); wz = fmaf(zv.x, w2t[k + 0], wz);
                hz = fmaf(zv.y, w1z[k + 1], hz); wz = fmaf(zv.y, w2t[k + 1], wz);
                hz = fmaf(zv.z, w1z[k + 2], hz); wz = fmaf(zv.z, w2t[k + 2], wz);
                hz = fmaf(zv.w, w1z[k + 3], hz); wz = fmaf(zv.w, w2t[k + 3], wz);
            }
            float h = fmaxf(Hj[bi] + hz, 0.f);
            part[n] = h * wz;
        }

#pragma unroll
        for (int n = 0; n < N_Z; n++) {
            float v = part[n];
            v += __shfl_xor_sync(0xffffffffu, v, 16);
            v += __shfl_xor_sync(0xffffffffu, v, 8);
            v += __shfl_xor_sync(0xffffffffu, v, 4);
            v += __shfl_xor_sync(0xffffffffu, v, 2);
            v += __shfl_xor_sync(0xffffffffu, v, 1);
            if (lane == 0) sRed[bi & 1][warp][n] = v;
        }
        __syncthreads();

        if (tid < N_Z) {
            float s = 0.f;
#pragma unroll
            for (int w = 0; w < 16; w++) s += sRed[bi & 1][w][tid];
            const float* zn = zb + tid * NOISE;
#pragma unroll
            for (int e = 0; e < NOISE; e++) s = fmaf(sP8[bi][e], zn[e], s);
            out[(b0 + bi) * N_Z + tid] = s;
        }
        // no second sync: next iteration writes the other sRed buffer
    }
}

// ---------------------------------------------------------------------------
extern "C" void kernel_launch(void* const* d_in, const int* in_sizes, int n_in,
                              void* d_out, int out_size) {
    const float* x    = (const float*)d_in[0];
    const float* feat = (const float*)d_in[1];
    const float* z    = (const float*)d_in[2];
    const float* Wep1 = (const float*)d_in[3];
    const float* bep1 = (const float*)d_in[4];
    const float* Wep2 = (const float*)d_in[5];
    const float* bep2 = (const float*)d_in[6];
    const float* Wp1  = (const float*)d_in[7];
    const float* bp1  = (const float*)d_in[8];
    const float* Wp2  = (const float*)d_in[9];
    const float* bp2  = (const float*)d_in[10];
    const float* Wp3  = (const float*)d_in[11];
    const float* bp3  = (const float*)d_in[12];
    float* out = (float*)d_out;

    cudaFuncSetAttribute(gemm_mma, cudaFuncAttributeMaxDynamicSharedMemorySize,
                         2 * BUF_STRIDE);

    convert_split_A<<<(B_DIM * KTOT / 4) / 256, 256>>>(x, feat);
    transpose_split_W<<<dim3(64, 16), dim3(32, 8)>>>(Wep1);
    repack_wp1<<<(STATE * PRI_N + 255) / 256, 256>>>(Wp1);
    gemm_mma<<<dim3(EPI_H / GM_BN, B_DIM / GM_BM), 256, 2 * BUF_STRIDE>>>(bep1);
    sgemm_prior<<<dim3(PRI_N / P_BN, B_DIM / P_BM), 128>>>(x, bp1);
    epilogue_kernel<<<B_DIM / 8, 512>>>(z, Wep1, Wep2, bep2, Wp2, bp2, Wp3, bp3, out);
}

// round 10
// speedup vs baseline: 1.0585x; 1.0585x over previous
#include <cuda_runtime.h>
#include <cuda_bf16.h>
#include <cstdint>

// Shapes
#define B_DIM 2048
#define N_Z 8
#define NOISE 32
#define STATE 1024
#define HID 1024
#define EPI_H 512
#define PRIOR_H 5
#define PRI_N 160   // 32 ensembles * 5
#define KTOT 2048   // xf concat length

typedef unsigned long long u64;

// ---- f32x2 helpers (prior gemm) ----
__device__ __forceinline__ u64 pk2(float lo, float hi) {
    u64 r; asm("mov.b64 %0,{%1,%2};" : "=l"(r) : "f"(lo), "f"(hi)); return r;
}
__device__ __forceinline__ u64 fma2(u64 a, u64 b, u64 c) {
    u64 d; asm("fma.rn.f32x2 %0,%1,%2,%3;" : "=l"(d) : "l"(a), "l"(b), "l"(c)); return d;
}
__device__ __forceinline__ float2 unpk(u64 v) {
    float2 r; asm("mov.b64 {%0,%1},%2;" : "=f"(r.x), "=f"(r.y) : "l"(v)); return r;
}

__device__ __forceinline__ uint32_t smem_u32(const void* p) {
    uint32_t a;
    asm("{ .reg .u64 t; cvta.to.shared.u64 t, %1; cvt.u32.u64 %0, t; }" : "=r"(a) : "l"(p));
    return a;
}

// ---- cp.async ----
#define CP16(dst, src) \
    asm volatile("cp.async.cg.shared.global [%0], [%1], 16;" :: "r"(dst), "l"(src))
#define CP_COMMIT() asm volatile("cp.async.commit_group;" ::: "memory")
#define CP_WAIT1() asm volatile("cp.async.wait_group 1;" ::: "memory")

// ---- Scratch (no allocation allowed) ----
__device__ float g_H[B_DIM * EPI_H];
__device__ float g_P1[B_DIM * PRI_N];
__device__ float g_W1r[STATE * PRI_N];
__device__ __align__(16) __nv_bfloat16 g_Ahi[B_DIM * KTOT];   // 8 MB
__device__ __align__(16) __nv_bfloat16 g_Alo[B_DIM * KTOT];   // 8 MB
__device__ __align__(16) __nv_bfloat16 g_Bhi[EPI_H * KTOT];   // 2 MB, [n][k]
__device__ __align__(16) __nv_bfloat16 g_Blo[EPI_H * KTOT];   // 2 MB

// ---------------------------------------------------------------------------
// Prep: split A = [x|feature] into bf16 hi/lo, row-major [2048][2048]
// ---------------------------------------------------------------------------
__global__ __launch_bounds__(256) void convert_split_A(
    const float* __restrict__ X, const float* __restrict__ F) {
    int i4 = blockIdx.x * 256 + threadIdx.x;
    int row = i4 >> 9;
    int c4 = i4 & 511;
    const float* src = (c4 < 256) ? (X + row * 1024 + c4 * 4)
                                  : (F + row * 1024 + (c4 - 256) * 4);
    float4 v = *(const float4*)src;
    __nv_bfloat16 h0 = __float2bfloat16_rn(v.x), h1 = __float2bfloat16_rn(v.y);
    __nv_bfloat16 h2 = __float2bfloat16_rn(v.z), h3 = __float2bfloat16_rn(v.w);
    __nv_bfloat16 l0 = __float2bfloat16_rn(v.x - __bfloat162float(h0));
    __nv_bfloat16 l1 = __float2bfloat16_rn(v.y - __bfloat162float(h1));
    __nv_bfloat16 l2 = __float2bfloat16_rn(v.z - __bfloat162float(h2));
    __nv_bfloat16 l3 = __float2bfloat16_rn(v.w - __bfloat162float(h3));
    __nv_bfloat162 ph0 = __halves2bfloat162(h0, h1), ph1 = __halves2bfloat162(h2, h3);
    __nv_bfloat162 pl0 = __halves2bfloat162(l0, l1), pl1 = __halves2bfloat162(l2, l3);
    uint2 uh; uh.x = *(uint32_t*)&ph0; uh.y = *(uint32_t*)&ph1;
    uint2 ul; ul.x = *(uint32_t*)&pl0; ul.y = *(uint32_t*)&pl1;
    size_t off = (size_t)row * KTOT + c4 * 4;
    *(uint2*)(g_Ahi + off) = uh;
    *(uint2*)(g_Alo + off) = ul;
}

// ---------------------------------------------------------------------------
// Prep: transpose+split W[0:2048][512] -> Bhi/Blo [512][2048]
// ---------------------------------------------------------------------------
__global__ __launch_bounds__(256) void transpose_split_W(const float* __restrict__ W) {
    __shared__ float t[32][33];
    int kt = blockIdx.x;   // 64
    int nt = blockIdx.y;   // 16
    int tx = threadIdx.x;  // 32
    int ty = threadIdx.y;  // 8
#pragma unroll
    for (int i = 0; i < 4; i++)
        t[ty * 4 + i][tx] = W[(size_t)(kt * 32 + ty * 4 + i) * EPI_H + nt * 32 + tx];
    __syncthreads();
#pragma unroll
    for (int i = 0; i < 4; i++) {
        int n = nt * 32 + ty * 4 + i;
        int k = kt * 32 + tx;
        float v = t[tx][ty * 4 + i];
        __nv_bfloat16 h = __float2bfloat16_rn(v);
        __nv_bfloat16 l = __float2bfloat16_rn(v - __bfloat162float(h));
        g_Bhi[(size_t)n * KTOT + k] = h;
        g_Blo[(size_t)n * KTOT + k] = l;
    }
}

// ---------------------------------------------------------------------------
// Repack Wp1[32][1024][5] -> W1r[1024][160]
// ---------------------------------------------------------------------------
__global__ void repack_wp1(const float* __restrict__ Wp1) {
    int idx = blockIdx.x * 256 + threadIdx.x;
    if (idx < STATE * PRI_N) {
        int k = idx / PRI_N;
        int c = idx - k * PRI_N;
        int e = c / PRIOR_H;
        int h = c - e * PRIOR_H;
        g_W1r[idx] = Wp1[e * (STATE * PRIOR_H) + k * PRIOR_H + h];
    }
}

// ---------------------------------------------------------------------------
// Tensor-core GEMM (bf16 3-pass hi/lo split), mma.sync m16n8k16.
// BM=64 BN=64 BK=64, 256 threads, 3-stage cp.async pipeline, 2 CTAs/SM.
// ---------------------------------------------------------------------------
#define GM_BM 64
#define GM_BN 64
#define GM_BK 64
#define NKB (KTOT / GM_BK)    // 32
#define SM_AHI 0
#define SM_ALO 8192
#define SM_BHI 16384
#define SM_BLO 24576
#define STAGE_B 32768         // 32 KB per stage
#define NSTAGE 3              // 96 KB total

__device__ __forceinline__ uint32_t swz(int r, int c) {
    return (uint32_t)(r * 128 + ((c ^ (r & 7)) * 16));
}
__device__ __forceinline__ void ldmx4(uint32_t addr, uint32_t* r) {
    asm volatile("ldmatrix.sync.aligned.m8n8.x4.shared.b16 {%0,%1,%2,%3}, [%4];"
        : "=r"(r[0]), "=r"(r[1]), "=r"(r[2]), "=r"(r[3]) : "r"(addr));
}
__device__ __forceinline__ void mma16816(float* c, const uint32_t* a,
                                         uint32_t b0, uint32_t b1) {
    asm volatile("mma.sync.aligned.m16n8k16.row.col.f32.bf16.bf16.f32 "
        "{%0,%1,%2,%3},{%4,%5,%6,%7},{%8,%9},{%0,%1,%2,%3};"
        : "+f"(c[0]), "+f"(c[1]), "+f"(c[2]), "+f"(c[3])
        : "r"(a[0]), "r"(a[1]), "r"(a[2]), "r"(a[3]), "r"(b0), "r"(b1));
}

__global__ __launch_bounds__(256, 2) void gemm_mma(const float* __restrict__ bias) {
    extern __shared__ char smem_raw[];
    const uint32_t sb = smem_u32(smem_raw);

    const int tid = threadIdx.x;
    const int lane = tid & 31;
    const int wid = tid >> 5;
    const int wm = wid & 1;        // 2 m-warps x 32 rows
    const int wn = wid >> 1;       // 4 n-warps x 16 cols
    const int row0 = blockIdx.y * GM_BM;
    const int col0 = blockIdx.x * GM_BN;

    // loader: 2 chunks (16B) per thread per tensor
    const int r0 = tid >> 3, c0 = tid & 7;            // ch = tid
    const int r1 = (tid + 256) >> 3, c1 = tid & 7;    // ch = tid+256
    const uint32_t o_a0 = swz(r0, c0), o_a1 = swz(r1, c1);

    // precompute gmem bases (element offsets advance by GM_BK per stage)
    const __nv_bfloat16* pAh0 = g_Ahi + (row0 + r0) * KTOT + c0 * 8;
    const __nv_bfloat16* pAh1 = g_Ahi + (row0 + r1) * KTOT + c1 * 8;
    const __nv_bfloat16* pAl0 = g_Alo + (row0 + r0) * KTOT + c0 * 8;
    const __nv_bfloat16* pAl1 = g_Alo + (row0 + r1) * KTOT + c1 * 8;
    const __nv_bfloat16* pBh0 = g_Bhi + (col0 + r0) * KTOT + c0 * 8;
    const __nv_bfloat16* pBh1 = g_Bhi + (col0 + r1) * KTOT + c1 * 8;
    const __nv_bfloat16* pBl0 = g_Blo + (col0 + r0) * KTOT + c0 * 8;
    const __nv_bfloat16* pBl1 = g_Blo + (col0 + r1) * KTOT + c1 * 8;

    float acc[2][2][4];
#pragma unroll
    for (int mi = 0; mi < 2; mi++)
#pragma unroll
        for (int nf = 0; nf < 2; nf++)
#pragma unroll
            for (int q = 0; q < 4; q++) acc[mi][nf][q] = 0.f;

    // issue stages 0 and 1
#pragma unroll
    for (int s = 0; s < 2; s++) {
        const uint32_t nb = sb + s * STAGE_B;
        const int ko = s * GM_BK;
        CP16(nb + SM_AHI + o_a0, pAh0 + ko);
        CP16(nb + SM_AHI + o_a1, pAh1 + ko);
        CP16(nb + SM_ALO + o_a0, pAl0 + ko);
        CP16(nb + SM_ALO + o_a1, pAl1 + ko);
        CP16(nb + SM_BHI + o_a0, pBh0 + ko);
        CP16(nb + SM_BHI + o_a1, pBh1 + ko);
        CP16(nb + SM_BLO + o_a0, pBl0 + ko);
        CP16(nb + SM_BLO + o_a1, pBl1 + ko);
        CP_COMMIT();
    }

    int slot = 0;
    for (int kb = 0; kb < NKB; kb++) {
        CP_WAIT1();
        __syncthreads();

        // issue stage kb+2 into slot (kb+2)%3
        if (kb + 2 < NKB) {
            int s2 = slot + 2; if (s2 >= NSTAGE) s2 -= NSTAGE;
            const uint32_t nb = sb + s2 * STAGE_B;
            const int ko = (kb + 2) * GM_BK;
            CP16(nb + SM_AHI + o_a0, pAh0 + ko);
            CP16(nb + SM_AHI + o_a1, pAh1 + ko);
            CP16(nb + SM_ALO + o_a0, pAl0 + ko);
            CP16(nb + SM_ALO + o_a1, pAl1 + ko);
            CP16(nb + SM_BHI + o_a0, pBh0 + ko);
            CP16(nb + SM_BHI + o_a1, pBh1 + ko);
            CP16(nb + SM_BLO + o_a0, pBl0 + ko);
            CP16(nb + SM_BLO + o_a1, pBl1 + ko);
        }
        CP_COMMIT();   // unconditional: keeps group accounting uniform

        // ---- compute on slot: 4 kblk of k16 ----
        const uint32_t bufb = sb + slot * STAGE_B;
        const int lrow = lane & 15;
#pragma unroll
        for (int kblk = 0; kblk < 4; kblk++) {
            const int ch = kblk * 2 + (lane >> 4);
            uint32_t ah[2][4], al[2][4], bh[4], bl[4];
#pragma unroll
            for (int mi = 0; mi < 2; mi++) {
                int r = wm * 32 + mi * 16 + lrow;
                uint32_t off = r * 128 + ((ch ^ (r & 7)) * 16);
                ldmx4(bufb + SM_AHI + off, ah[mi]);
                ldmx4(bufb + SM_ALO + off, al[mi]);
            }
            {
                int r = wn * 16 + lrow;
                uint32_t off = r * 128 + ((ch ^ (r & 7)) * 16);
                ldmx4(bufb + SM_BHI + off, bh);
                ldmx4(bufb + SM_BLO + off, bl);
            }
#pragma unroll
            for (int mi = 0; mi < 2; mi++)
#pragma unroll
                for (int nf = 0; nf < 2; nf++) {
                    mma16816(acc[mi][nf], ah[mi], bh[nf], bh[nf + 2]);
                    mma16816(acc[mi][nf], ah[mi], bl[nf], bl[nf + 2]);
                    mma16816(acc[mi][nf], al[mi], bh[nf], bh[nf + 2]);
                }
        }

        slot++; if (slot >= NSTAGE) slot = 0;
    }

    // ---- epilogue: add bias, store to g_H ----
#pragma unroll
    for (int mi = 0; mi < 2; mi++)
#pragma unroll
        for (int nf = 0; nf < 2; nf++) {
            int r = row0 + wm * 32 + mi * 16 + (lane >> 2);
            int cc = col0 + wn * 16 + nf * 8 + (lane & 3) * 2;
            float2 b2 = *(const float2*)(bias + cc);
            float2 v0, v1;
            v0.x = acc[mi][nf][0] + b2.x; v0.y = acc[mi][nf][1] + b2.y;
            v1.x = acc[mi][nf][2] + b2.x; v1.y = acc[mi][nf][3] + b2.y;
            *(float2*)(g_H + r * EPI_H + cc) = v0;
            *(float2*)(g_H + (r + 8) * EPI_H + cc) = v1;
        }
}

// ---------------------------------------------------------------------------
// Prior GEMM: g_P1[2048][160] = relu(x @ g_W1r + bp1)   (f32x2)
// ---------------------------------------------------------------------------
#define P_BM 64
#define P_BN 32
#define P_BK 16
__global__ __launch_bounds__(128) void sgemm_prior(
    const float* __restrict__ X, const float* __restrict__ bp1) {
    __shared__ float As[2][P_BK][P_BM + 4];
    __shared__ float Bs[2][P_BK][P_BN];

    const int tid = threadIdx.x;
    const int row0 = blockIdx.y * P_BM;
    const int col0 = blockIdx.x * P_BN;

    const int ar = tid >> 2;
    const int ac4 = tid & 3;
    const int bkr = tid >> 3;
    const int bjc = tid & 7;
    const int ty = tid >> 3;
    const int tx = tid & 7;

    u64 acc2[2][4];
#pragma unroll
    for (int i = 0; i < 2; i++)
#pragma unroll
        for (int j = 0; j < 4; j++) acc2[i][j] = 0ULL;

    float4 pa0, pa1, pb;
    {
        int k = ac4 * 4;
        pa0 = *(const float4*)(X + (row0 + ar) * STATE + k);
        pa1 = *(const float4*)(X + (row0 + ar + 32) * STATE + k);
        pb  = *(const float4*)(g_W1r + bkr * PRI_N + col0 + bjc * 4);
    }
    {
        As[0][ac4 * 4 + 0][ar] = pa0.x; As[0][ac4 * 4 + 1][ar] = pa0.y;
        As[0][ac4 * 4 + 2][ar] = pa0.z; As[0][ac4 * 4 + 3][ar] = pa0.w;
        As[0][ac4 * 4 + 0][ar + 32] = pa1.x; As[0][ac4 * 4 + 1][ar + 32] = pa1.y;
        As[0][ac4 * 4 + 2][ar + 32] = pa1.z; As[0][ac4 * 4 + 3][ar + 32] = pa1.w;
        *(float4*)&Bs[0][bkr][bjc * 4] = pb;
    }
    __syncthreads();

    const int NT = STATE / P_BK;
    int buf = 0;
    for (int kt = 0; kt < NT; kt++) {
        if (kt + 1 < NT) {
            int kg = (kt + 1) * P_BK + ac4 * 4;
            pa0 = *(const float4*)(X + (row0 + ar) * STATE + kg);
            pa1 = *(const float4*)(X + (row0 + ar + 32) * STATE + kg);
            pb  = *(const float4*)(g_W1r + ((kt + 1) * P_BK + bkr) * PRI_N + col0 + bjc * 4);
        }
#pragma unroll
        for (int kk = 0; kk < P_BK; kk++) {
            ulonglong2 aa = *(const ulonglong2*)&As[buf][kk][ty * 4];
            float4 rb = *(const float4*)&Bs[buf][kk][tx * 4];
            u64 a2[2] = {aa.x, aa.y};
            u64 bd[4];
            bd[0] = pk2(rb.x, rb.x); bd[1] = pk2(rb.y, rb.y);
            bd[2] = pk2(rb.z, rb.z); bd[3] = pk2(rb.w, rb.w);
#pragma unroll
            for (int i = 0; i < 2; i++)
#pragma unroll
                for (int j = 0; j < 4; j++)
                    acc2[i][j] = fma2(a2[i], bd[j], acc2[i][j]);
        }
        if (kt + 1 < NT) {
            int nb = buf ^ 1;
            As[nb][ac4 * 4 + 0][ar] = pa0.x; As[nb][ac4 * 4 + 1][ar] = pa0.y;
            As[nb][ac4 * 4 + 2][ar] = pa0.z; As[nb][ac4 * 4 + 3][ar] = pa0.w;
            As[nb][ac4 * 4 + 0][ar + 32] = pa1.x; As[nb][ac4 * 4 + 1][ar + 32] = pa1.y;
            As[nb][ac4 * 4 + 2][ar + 32] = pa1.z; As[nb][ac4 * 4 + 3][ar + 32] = pa1.w;
            *(float4*)&Bs[nb][bkr][bjc * 4] = pb;
        }
        __syncthreads();
        buf ^= 1;
    }

    float4 bv = *(const float4*)(bp1 + col0 + tx * 4);
#pragma unroll
    for (int i2 = 0; i2 < 2; i2++) {
        float2 u0 = unpk(acc2[i2][0]), u1 = unpk(acc2[i2][1]);
        float2 u2 = unpk(acc2[i2][2]), u3 = unpk(acc2[i2][3]);
        int r = row0 + ty * 4 + 2 * i2;
        float4 olo, ohi;
        olo.x = fmaxf(u0.x + bv.x, 0.f); olo.y = fmaxf(u1.x + bv.y, 0.f);
        olo.z = fmaxf(u2.x + bv.z, 0.f); olo.w = fmaxf(u3.x + bv.w, 0.f);
        ohi.x = fmaxf(u0.y + bv.x, 0.f); ohi.y = fmaxf(u1.y + bv.y, 0.f);
        ohi.z = fmaxf(u2.y + bv.z, 0.f); ohi.w = fmaxf(u3.y + bv.w, 0.f);
        *(float4*)(g_P1 + r * PRI_N + col0 + tx * 4) = olo;
        *(float4*)(g_P1 + (r + 1) * PRI_N + col0 + tx * 4) = ohi;
    }
}

// ---------------------------------------------------------------------------
// Fused epilogue (R2/R6 form, measured 52.3us)
// ---------------------------------------------------------------------------
__global__ __launch_bounds__(512, 1) void epilogue_kernel(
    const float* __restrict__ Z, const float* __restrict__ Wep1,
    const float* __restrict__ Wep2, const float* __restrict__ bep2,
    const float* __restrict__ Wp2, const float* __restrict__ bp2,
    const float* __restrict__ Wp3, const float* __restrict__ bp3,
    float* __restrict__ out) {
    __shared__ __align__(16) float sZ[N_Z * NOISE];
    __shared__ float sP[NOISE];
    __shared__ float sRed[16][N_Z];

    const int tid = threadIdx.x;
    const int j = tid;
    const int lane = tid & 31;
    const int warp = tid >> 5;
    const int b0 = blockIdx.x * 8;

    float w1z[NOISE];
    float w2t[NOISE];
#pragma unroll
    for (int k = 0; k < NOISE; k++)
        w1z[k] = Wep1[(2048 + k) * EPI_H + j];
#pragma unroll
    for (int k4 = 0; k4 < NOISE / 4; k4++) {
        float4 v = *(const float4*)(Wep2 + j * NOISE + k4 * 4);
        w2t[k4 * 4 + 0] = v.x; w2t[k4 * 4 + 1] = v.y;
        w2t[k4 * 4 + 2] = v.z; w2t[k4 * 4 + 3] = v.w;
    }

    for (int bi = 0; bi < 8; bi++) {
        const int b = b0 + bi;
        const float Hj = g_H[b * EPI_H + j];

        if (tid >= 256) {
            int t = tid - 256;
            sZ[t] = Z[b * (N_Z * NOISE) + t];
        } else if (tid < 32) {
            int e = tid;
            const float* p1 = g_P1 + b * PRI_N + e * PRIOR_H;
            float h1[PRIOR_H];
#pragma unroll
            for (int h = 0; h < PRIOR_H; h++) h1[h] = p1[h];
            float h2[PRIOR_H];
#pragma unroll
            for (int g = 0; g < PRIOR_H; g++) {
                float s = bp2[e * PRIOR_H + g];
#pragma unroll
                for (int h = 0; h < PRIOR_H; h++)
                    s = fmaf(h1[h], Wp2[e * 25 + h * PRIOR_H + g], s);
                h2[g] = fmaxf(s, 0.f);
            }
            float p = bp3[e];
#pragma unroll
            for (int g = 0; g < PRIOR_H; g++)
                p = fmaf(h2[g], Wp3[e * PRIOR_H + g], p);
            sP[e] = p + bep2[e];
        }
        __syncthreads();

        float part[N_Z];
#pragma unroll
        for (int n = 0; n < N_Z; n++) {
            float hz = 0.f, wz = 0.f;
            const float4* z4 = (const float4*)(sZ + n * NOISE);
#pragma unroll
            for (int k4 = 0; k4 < NOISE / 4; k4++) {
                float4 zv = z4[k4];
                int k = k4 * 4;
                hz = fmaf(zv.x, w1z[k + 0], hz); wz = fmaf(zv.x, w2t[k + 0], wz);
                hz = fmaf(zv.y, w1z[k + 1], hz); wz = fmaf(zv.y, w2t[k + 1], wz);
                hz = fmaf(zv.z, w1z[k + 2], hz); wz = fmaf(zv.z, w2t[k + 2], wz);
                hz = fmaf(zv.w, w1z[k + 3], hz); wz = fmaf(zv.w, w2t[k + 3], wz);
            }
            float h = fmaxf(Hj + hz, 0.f);
            part[n] = h * wz;
        }

#pragma unroll
        for (int n = 0; n < N_Z; n++) {
            float v = part[n];
            v += __shfl_xor_sync(0xffffffffu, v, 16);
            v += __shfl_xor_sync(0xffffffffu, v, 8);
            v += __shfl_xor_sync(0xffffffffu, v, 4);
            v += __shfl_xor_sync(0xffffffffu, v, 2);
            v += __shfl_xor_sync(0xffffffffu, v, 1);
            if (lane == 0) sRed[warp][n] = v;
        }
        __syncthreads();

        if (tid < N_Z) {
            float s = 0.f;
#pragma unroll
            for (int w = 0; w < 16; w++) s += sRed[w][tid];
            const float* zn = sZ + tid * NOISE;
#pragma unroll
            for (int e = 0; e < NOISE; e++) s = fmaf(sP[e], zn[e], s);
            out[b * N_Z + tid] = s;
        }
        __syncthreads();
    }
}

// ---------------------------------------------------------------------------
extern "C" void kernel_launch(void* const* d_in, const int* in_sizes, int n_in,
                              void* d_out, int out_size) {
    const float* x    = (const float*)d_in[0];
    const float* feat = (const float*)d_in[1];
    const float* z    = (const float*)d_in[2];
    const float* Wep1 = (const float*)d_in[3];
    const float* bep1 = (const float*)d_in[4];
    const float* Wep2 = (const float*)d_in[5];
    const float* bep2 = (const float*)d_in[6];
    const float* Wp1  = (const float*)d_in[7];
    const float* bp1  = (const float*)d_in[8];
    const float* Wp2  = (const float*)d_in[9];
    const float* bp2  = (const float*)d_in[10];
    const float* Wp3  = (const float*)d_in[11];
    const float* bp3  = (const float*)d_in[12];
    float* out = (float*)d_out;

    cudaFuncSetAttribute(gemm_mma, cudaFuncAttributeMaxDynamicSharedMemorySize,
                         NSTAGE * STAGE_B);

    convert_split_A<<<(B_DIM * KTOT / 4) / 256, 256>>>(x, feat);
    transpose_split_W<<<dim3(64, 16), dim3(32, 8)>>>(Wep1);
    repack_wp1<<<(STATE * PRI_N + 255) / 256, 256>>>(Wp1);
    gemm_mma<<<dim3(EPI_H / GM_BN, B_DIM / GM_BM), 256, NSTAGE * STAGE_B>>>(bep1);
    sgemm_prior<<<dim3(PRI_N / P_BN, B_DIM / P_BM), 128>>>(x, bp1);
    epilogue_kernel<<<B_DIM / 8, 512>>>(z, Wep1, Wep2, bep2, Wp2, bp2, Wp3, bp3, out);
}

// round 11
// speedup vs baseline: 1.0876x; 1.0275x over previous
#include <cuda_runtime.h>
#include <cuda_bf16.h>
#include <cstdint>

// Shapes
#define B_DIM 2048
#define N_Z 8
#define NOISE 32
#define STATE 1024
#define HID 1024
#define EPI_H 512
#define PRIOR_H 5
#define PRI_N 160   // 32 ensembles * 5
#define KTOT 2048   // xf concat length

typedef unsigned long long u64;

// ---- f32x2 helpers (prior gemm) ----
__device__ __forceinline__ u64 pk2(float lo, float hi) {
    u64 r; asm("mov.b64 %0,{%1,%2};" : "=l"(r) : "f"(lo), "f"(hi)); return r;
}
__device__ __forceinline__ u64 fma2(u64 a, u64 b, u64 c) {
    u64 d; asm("fma.rn.f32x2 %0,%1,%2,%3;" : "=l"(d) : "l"(a), "l"(b), "l"(c)); return d;
}
__device__ __forceinline__ float2 unpk(u64 v) {
    float2 r; asm("mov.b64 {%0,%1},%2;" : "=f"(r.x), "=f"(r.y) : "l"(v)); return r;
}

__device__ __forceinline__ uint32_t smem_u32(const void* p) {
    uint32_t a;
    asm("{ .reg .u64 t; cvta.to.shared.u64 t, %1; cvt.u32.u64 %0, t; }" : "=r"(a) : "l"(p));
    return a;
}

// ---- cp.async ----
#define CP16(dst, src) \
    asm volatile("cp.async.cg.shared.global [%0], [%1], 16;" :: "r"(dst), "l"(src))
#define CP_COMMIT() asm volatile("cp.async.commit_group;" ::: "memory")
#define CP_WAIT1() asm volatile("cp.async.wait_group 1;" ::: "memory")

// ---- Scratch (no allocation allowed) ----
__device__ float g_H[B_DIM * EPI_H];
__device__ float g_P1[B_DIM * PRI_N];
__device__ float g_W1r[STATE * PRI_N];
__device__ __align__(16) __nv_bfloat16 g_Ahi[B_DIM * KTOT];   // 8 MB
__device__ __align__(16) __nv_bfloat16 g_Alo[B_DIM * KTOT];   // 8 MB
__device__ __align__(16) __nv_bfloat16 g_Bhi[EPI_H * KTOT];   // 2 MB, [n][k]
__device__ __align__(16) __nv_bfloat16 g_Blo[EPI_H * KTOT];   // 2 MB

// ---------------------------------------------------------------------------
// Prep: split A = [x|feature] into bf16 hi/lo, row-major [2048][2048]
// ---------------------------------------------------------------------------
__global__ __launch_bounds__(256) void convert_split_A(
    const float* __restrict__ X, const float* __restrict__ F) {
    int i4 = blockIdx.x * 256 + threadIdx.x;
    int row = i4 >> 9;
    int c4 = i4 & 511;
    const float* src = (c4 < 256) ? (X + row * 1024 + c4 * 4)
                                  : (F + row * 1024 + (c4 - 256) * 4);
    float4 v = *(const float4*)src;
    __nv_bfloat16 h0 = __float2bfloat16_rn(v.x), h1 = __float2bfloat16_rn(v.y);
    __nv_bfloat16 h2 = __float2bfloat16_rn(v.z), h3 = __float2bfloat16_rn(v.w);
    __nv_bfloat16 l0 = __float2bfloat16_rn(v.x - __bfloat162float(h0));
    __nv_bfloat16 l1 = __float2bfloat16_rn(v.y - __bfloat162float(h1));
    __nv_bfloat16 l2 = __float2bfloat16_rn(v.z - __bfloat162float(h2));
    __nv_bfloat16 l3 = __float2bfloat16_rn(v.w - __bfloat162float(h3));
    __nv_bfloat162 ph0 = __halves2bfloat162(h0, h1), ph1 = __halves2bfloat162(h2, h3);
    __nv_bfloat162 pl0 = __halves2bfloat162(l0, l1), pl1 = __halves2bfloat162(l2, l3);
    uint2 uh; uh.x = *(uint32_t*)&ph0; uh.y = *(uint32_t*)&ph1;
    uint2 ul; ul.x = *(uint32_t*)&pl0; ul.y = *(uint32_t*)&pl1;
    size_t off = (size_t)row * KTOT + c4 * 4;
    *(uint2*)(g_Ahi + off) = uh;
    *(uint2*)(g_Alo + off) = ul;
}

// ---------------------------------------------------------------------------
// Prep: transpose+split W[0:2048][512] -> Bhi/Blo [512][2048]
// ---------------------------------------------------------------------------
__global__ __launch_bounds__(256) void transpose_split_W(const float* __restrict__ W) {
    __shared__ float t[32][33];
    int kt = blockIdx.x;   // 64
    int nt = blockIdx.y;   // 16
    int tx = threadIdx.x;  // 32
    int ty = threadIdx.y;  // 8
#pragma unroll
    for (int i = 0; i < 4; i++)
        t[ty * 4 + i][tx] = W[(size_t)(kt * 32 + ty * 4 + i) * EPI_H + nt * 32 + tx];
    __syncthreads();
#pragma unroll
    for (int i = 0; i < 4; i++) {
        int n = nt * 32 + ty * 4 + i;
        int k = kt * 32 + tx;
        float v = t[tx][ty * 4 + i];
        __nv_bfloat16 h = __float2bfloat16_rn(v);
        __nv_bfloat16 l = __float2bfloat16_rn(v - __bfloat162float(h));
        g_Bhi[(size_t)n * KTOT + k] = h;
        g_Blo[(size_t)n * KTOT + k] = l;
    }
}

// ---------------------------------------------------------------------------
// Repack Wp1[32][1024][5] -> W1r[1024][160]
// ---------------------------------------------------------------------------
__global__ void repack_wp1(const float* __restrict__ Wp1) {
    int idx = blockIdx.x * 256 + threadIdx.x;
    if (idx < STATE * PRI_N) {
        int k = idx / PRI_N;
        int c = idx - k * PRI_N;
        int e = c / PRIOR_H;
        int h = c - e * PRIOR_H;
        g_W1r[idx] = Wp1[e * (STATE * PRIOR_H) + k * PRIOR_H + h];
    }
}

// ---------------------------------------------------------------------------
// Tensor-core GEMM (bf16 3-pass hi/lo split), mma.sync m16n8k16.
// BM=64 BN=64 BK=64, 128 threads (4 warps, warp tile 32x32 -> 8 acc chains),
// 3-stage cp.async pipeline, 2 CTAs/SM.
// ---------------------------------------------------------------------------
#define GM_BM 64
#define GM_BN 64
#define GM_BK 64
#define NKB (KTOT / GM_BK)    // 32
#define SM_AHI 0
#define SM_ALO 8192
#define SM_BHI 16384
#define SM_BLO 24576
#define STAGE_B 32768         // 32 KB per stage
#define NSTAGE 3              // 96 KB total
#define GM_THREADS 128

__device__ __forceinline__ uint32_t swz(int r, int c) {
    return (uint32_t)(r * 128 + ((c ^ (r & 7)) * 16));
}
__device__ __forceinline__ void ldmx4(uint32_t addr, uint32_t* r) {
    asm volatile("ldmatrix.sync.aligned.m8n8.x4.shared.b16 {%0,%1,%2,%3}, [%4];"
        : "=r"(r[0]), "=r"(r[1]), "=r"(r[2]), "=r"(r[3]) : "r"(addr));
}
__device__ __forceinline__ void mma16816(float* c, const uint32_t* a,
                                         uint32_t b0, uint32_t b1) {
    asm volatile("mma.sync.aligned.m16n8k16.row.col.f32.bf16.bf16.f32 "
        "{%0,%1,%2,%3},{%4,%5,%6,%7},{%8,%9},{%0,%1,%2,%3};"
        : "+f"(c[0]), "+f"(c[1]), "+f"(c[2]), "+f"(c[3])
        : "r"(a[0]), "r"(a[1]), "r"(a[2]), "r"(a[3]), "r"(b0), "r"(b1));
}

// issue one full stage of cp.async loads (16 chunks per thread)
__device__ __forceinline__ void issue_stage(uint32_t nb, int ko, int tid,
                                            int row0, int col0) {
#pragma unroll
    for (int i = 0; i < 4; i++) {
        int ch = tid + i * GM_THREADS;
        int r = ch >> 3, c = ch & 7;
        uint32_t o = swz(r, c);
        CP16(nb + SM_AHI + o, g_Ahi + (row0 + r) * KTOT + ko + c * 8);
        CP16(nb + SM_ALO + o, g_Alo + (row0 + r) * KTOT + ko + c * 8);
        CP16(nb + SM_BHI + o, g_Bhi + (col0 + r) * KTOT + ko + c * 8);
        CP16(nb + SM_BLO + o, g_Blo + (col0 + r) * KTOT + ko + c * 8);
    }
}

__global__ __launch_bounds__(GM_THREADS, 2) void gemm_mma(const float* __restrict__ bias) {
    extern __shared__ char smem_raw[];
    const uint32_t sb = smem_u32(smem_raw);

    const int tid = threadIdx.x;
    const int lane = tid & 31;
    const int wid = tid >> 5;
    const int wm = wid & 1;        // 2 m-warps x 32 rows
    const int wn = wid >> 1;       // 2 n-warps x 32 cols
    const int row0 = blockIdx.y * GM_BM;
    const int col0 = blockIdx.x * GM_BN;

    float acc[2][4][4];
#pragma unroll
    for (int mi = 0; mi < 2; mi++)
#pragma unroll
        for (int nf = 0; nf < 4; nf++)
#pragma unroll
            for (int q = 0; q < 4; q++) acc[mi][nf][q] = 0.f;

    // issue stages 0 and 1
    issue_stage(sb, 0, tid, row0, col0);
    CP_COMMIT();
    issue_stage(sb + STAGE_B, GM_BK, tid, row0, col0);
    CP_COMMIT();

    int slot = 0;
    for (int kb = 0; kb < NKB; kb++) {
        CP_WAIT1();
        __syncthreads();

        if (kb + 2 < NKB) {
            int s2 = slot + 2; if (s2 >= NSTAGE) s2 -= NSTAGE;
            issue_stage(sb + s2 * STAGE_B, (kb + 2) * GM_BK, tid, row0, col0);
        }
        CP_COMMIT();

        // ---- compute on slot: 4 kblk of k16 ----
        const uint32_t bufb = sb + slot * STAGE_B;
        const int lrow = lane & 15;
#pragma unroll
        for (int kblk = 0; kblk < 4; kblk++) {
            const int ch = kblk * 2 + (lane >> 4);
            uint32_t ah[2][4], al[2][4], bh[2][4], bl[2][4];
#pragma unroll
            for (int mi = 0; mi < 2; mi++) {
                int r = wm * 32 + mi * 16 + lrow;
                uint32_t off = r * 128 + ((ch ^ (r & 7)) * 16);
                ldmx4(bufb + SM_AHI + off, ah[mi]);
                ldmx4(bufb + SM_ALO + off, al[mi]);
            }
#pragma unroll
            for (int ni = 0; ni < 2; ni++) {
                int r = wn * 32 + ni * 16 + lrow;
                uint32_t off = r * 128 + ((ch ^ (r & 7)) * 16);
                ldmx4(bufb + SM_BHI + off, bh[ni]);
                ldmx4(bufb + SM_BLO + off, bl[ni]);
            }
#pragma unroll
            for (int mi = 0; mi < 2; mi++)
#pragma unroll
                for (int ni = 0; ni < 2; ni++)
#pragma unroll
                    for (int s = 0; s < 2; s++) {
                        float* a = acc[mi][ni * 2 + s];
                        mma16816(a, ah[mi], bh[ni][s], bh[ni][s + 2]);
                        mma16816(a, ah[mi], bl[ni][s], bl[ni][s + 2]);
                        mma16816(a, al[mi], bh[ni][s], bh[ni][s + 2]);
                    }
        }

        slot++; if (slot >= NSTAGE) slot = 0;
    }

    // ---- epilogue: add bias, store to g_H ----
#pragma unroll
    for (int mi = 0; mi < 2; mi++)
#pragma unroll
        for (int nf = 0; nf < 4; nf++) {
            int r = row0 + wm * 32 + mi * 16 + (lane >> 2);
            int cc = col0 + wn * 32 + nf * 8 + (lane & 3) * 2;
            float2 b2 = *(const float2*)(bias + cc);
            float2 v0, v1;
            v0.x = acc[mi][nf][0] + b2.x; v0.y = acc[mi][nf][1] + b2.y;
            v1.x = acc[mi][nf][2] + b2.x; v1.y = acc[mi][nf][3] + b2.y;
            *(float2*)(g_H + r * EPI_H + cc) = v0;
            *(float2*)(g_H + (r + 8) * EPI_H + cc) = v1;
        }
}

// ---------------------------------------------------------------------------
// Prior GEMM: g_P1[2048][160] = relu(x @ g_W1r + bp1)   (f32x2)
// ---------------------------------------------------------------------------
#define P_BM 64
#define P_BN 32
#define P_BK 16
__global__ __launch_bounds__(128) void sgemm_prior(
    const float* __restrict__ X, const float* __restrict__ bp1) {
    __shared__ float As[2][P_BK][P_BM + 4];
    __shared__ float Bs[2][P_BK][P_BN];

    const int tid = threadIdx.x;
    const int row0 = blockIdx.y * P_BM;
    const int col0 = blockIdx.x * P_BN;

    const int ar = tid >> 2;
    const int ac4 = tid & 3;
    const int bkr = tid >> 3;
    const int bjc = tid & 7;
    const int ty = tid >> 3;
    const int tx = tid & 7;

    u64 acc2[2][4];
#pragma unroll
    for (int i = 0; i < 2; i++)
#pragma unroll
        for (int j = 0; j < 4; j++) acc2[i][j] = 0ULL;

    float4 pa0, pa1, pb;
    {
        int k = ac4 * 4;
        pa0 = *(const float4*)(X + (row0 + ar) * STATE + k);
        pa1 = *(const float4*)(X + (row0 + ar + 32) * STATE + k);
        pb  = *(const float4*)(g_W1r + bkr * PRI_N + col0 + bjc * 4);
    }
    {
        As[0][ac4 * 4 + 0][ar] = pa0.x; As[0][ac4 * 4 + 1][ar] = pa0.y;
        As[0][ac4 * 4 + 2][ar] = pa0.z; As[0][ac4 * 4 + 3][ar] = pa0.w;
        As[0][ac4 * 4 + 0][ar + 32] = pa1.x; As[0][ac4 * 4 + 1][ar + 32] = pa1.y;
        As[0][ac4 * 4 + 2][ar + 32] = pa1.z; As[0][ac4 * 4 + 3][ar + 32] = pa1.w;
        *(float4*)&Bs[0][bkr][bjc * 4] = pb;
    }
    __syncthreads();

    const int NT = STATE / P_BK;
    int buf = 0;
    for (int kt = 0; kt < NT; kt++) {
        if (kt + 1 < NT) {
            int kg = (kt + 1) * P_BK + ac4 * 4;
            pa0 = *(const float4*)(X + (row0 + ar) * STATE + kg);
            pa1 = *(const float4*)(X + (row0 + ar + 32) * STATE + kg);
            pb  = *(const float4*)(g_W1r + ((kt + 1) * P_BK + bkr) * PRI_N + col0 + bjc * 4);
        }
#pragma unroll
        for (int kk = 0; kk < P_BK; kk++) {
            ulonglong2 aa = *(const ulonglong2*)&As[buf][kk][ty * 4];
            float4 rb = *(const float4*)&Bs[buf][kk][tx * 4];
            u64 a2[2] = {aa.x, aa.y};
            u64 bd[4];
            bd[0] = pk2(rb.x, rb.x); bd[1] = pk2(rb.y, rb.y);
            bd[2] = pk2(rb.z, rb.z); bd[3] = pk2(rb.w, rb.w);
#pragma unroll
            for (int i = 0; i < 2; i++)
#pragma unroll
                for (int j = 0; j < 4; j++)
                    acc2[i][j] = fma2(a2[i], bd[j], acc2[i][j]);
        }
        if (kt + 1 < NT) {
            int nb = buf ^ 1;
            As[nb][ac4 * 4 + 0][ar] = pa0.x; As[nb][ac4 * 4 + 1][ar] = pa0.y;
            As[nb][ac4 * 4 + 2][ar] = pa0.z; As[nb][ac4 * 4 + 3][ar] = pa0.w;
            As[nb][ac4 * 4 + 0][ar + 32] = pa1.x; As[nb][ac4 * 4 + 1][ar + 32] = pa1.y;
            As[nb][ac4 * 4 + 2][ar + 32] = pa1.z; As[nb][ac4 * 4 + 3][ar + 32] = pa1.w;
            *(float4*)&Bs[nb][bkr][bjc * 4] = pb;
        }
        __syncthreads();
        buf ^= 1;
    }

    float4 bv = *(const float4*)(bp1 + col0 + tx * 4);
#pragma unroll
    for (int i2 = 0; i2 < 2; i2++) {
        float2 u0 = unpk(acc2[i2][0]), u1 = unpk(acc2[i2][1]);
        float2 u2 = unpk(acc2[i2][2]), u3 = unpk(acc2[i2][3]);
        int r = row0 + ty * 4 + 2 * i2;
        float4 olo, ohi;
        olo.x = fmaxf(u0.x + bv.x, 0.f); olo.y = fmaxf(u1.x + bv.y, 0.f);
        olo.z = fmaxf(u2.x + bv.z, 0.f); olo.w = fmaxf(u3.x + bv.w, 0.f);
        ohi.x = fmaxf(u0.y + bv.x, 0.f); ohi.y = fmaxf(u1.y + bv.y, 0.f);
        ohi.z = fmaxf(u2.y + bv.z, 0.f); ohi.w = fmaxf(u3.y + bv.w, 0.f);
        *(float4*)(g_P1 + r * PRI_N + col0 + tx * 4) = olo;
        *(float4*)(g_P1 + (r + 1) * PRI_N + col0 + tx * 4) = ohi;
    }
}

// ---------------------------------------------------------------------------
// Fused epilogue (R2/R6 form, measured 52.3us)
// ---------------------------------------------------------------------------
__global__ __launch_bounds__(512, 1) void epilogue_kernel(
    const float* __restrict__ Z, const float* __restrict__ Wep1,
    const float* __restrict__ Wep2, const float* __restrict__ bep2,
    const float* __restrict__ Wp2, const float* __restrict__ bp2,
    const float* __restrict__ Wp3, const float* __restrict__ bp3,
    float* __restrict__ out) {
    __shared__ __align__(16) float sZ[N_Z * NOISE];
    __shared__ float sP[NOISE];
    __shared__ float sRed[16][N_Z];

    const int tid = threadIdx.x;
    const int j = tid;
    const int lane = tid & 31;
    const int warp = tid >> 5;
    const int b0 = blockIdx.x * 8;

    float w1z[NOISE];
    float w2t[NOISE];
#pragma unroll
    for (int k = 0; k < NOISE; k++)
        w1z[k] = Wep1[(2048 + k) * EPI_H + j];
#pragma unroll
    for (int k4 = 0; k4 < NOISE / 4; k4++) {
        float4 v = *(const float4*)(Wep2 + j * NOISE + k4 * 4);
        w2t[k4 * 4 + 0] = v.x; w2t[k4 * 4 + 1] = v.y;
        w2t[k4 * 4 + 2] = v.z; w2t[k4 * 4 + 3] = v.w;
    }

    for (int bi = 0; bi < 8; bi++) {
        const int b = b0 + bi;
        const float Hj = g_H[b * EPI_H + j];

        if (tid >= 256) {
            int t = tid - 256;
            sZ[t] = Z[b * (N_Z * NOISE) + t];
        } else if (tid < 32) {
            int e = tid;
            const float* p1 = g_P1 + b * PRI_N + e * PRIOR_H;
            float h1[PRIOR_H];
#pragma unroll
            for (int h = 0; h < PRIOR_H; h++) h1[h] = p1[h];
            float h2[PRIOR_H];
#pragma unroll
            for (int g = 0; g < PRIOR_H; g++) {
                float s = bp2[e * PRIOR_H + g];
#pragma unroll
                for (int h = 0; h < PRIOR_H; h++)
                    s = fmaf(h1[h], Wp2[e * 25 + h * PRIOR_H + g], s);
                h2[g] = fmaxf(s, 0.f);
            }
            float p = bp3[e];
#pragma unroll
            for (int g = 0; g < PRIOR_H; g++)
                p = fmaf(h2[g], Wp3[e * PRIOR_H + g], p);
            sP[e] = p + bep2[e];
        }
        __syncthreads();

        float part[N_Z];
#pragma unroll
        for (int n = 0; n < N_Z; n++) {
            float hz = 0.f, wz = 0.f;
            const float4* z4 = (const float4*)(sZ + n * NOISE);
#pragma unroll
            for (int k4 = 0; k4 < NOISE / 4; k4++) {
                float4 zv = z4[k4];
                int k = k4 * 4;
                hz = fmaf(zv.x, w1z[k + 0], hz); wz = fmaf(zv.x, w2t[k + 0], wz);
                hz = fmaf(zv.y, w1z[k + 1], hz); wz = fmaf(zv.y, w2t[k + 1], wz);
                hz = fmaf(zv.z, w1z[k + 2], hz); wz = fmaf(zv.z, w2t[k + 2], wz);
                hz = fmaf(zv.w, w1z[k + 3], hz); wz = fmaf(zv.w, w2t[k + 3], wz);
            }
            float h = fmaxf(Hj + hz, 0.f);
            part[n] = h * wz;
        }

#pragma unroll
        for (int n = 0; n < N_Z; n++) {
            float v = part[n];
            v += __shfl_xor_sync(0xffffffffu, v, 16);
            v += __shfl_xor_sync(0xffffffffu, v, 8);
            v += __shfl_xor_sync(0xffffffffu, v, 4);
            v += __shfl_xor_sync(0xffffffffu, v, 2);
            v += __shfl_xor_sync(0xffffffffu, v, 1);
            if (lane == 0) sRed[warp][n] = v;
        }
        __syncthreads();

        if (tid < N_Z) {
            float s = 0.f;
#pragma unroll
            for (int w = 0; w < 16; w++) s += sRed[w][tid];
            const float* zn = sZ + tid * NOISE;
#pragma unroll
            for (int e = 0; e < NOISE; e++) s = fmaf(sP[e], zn[e], s);
            out[b * N_Z + tid] = s;
        }
        __syncthreads();
    }
}

// ---------------------------------------------------------------------------
extern "C" void kernel_launch(void* const* d_in, const int* in_sizes, int n_in,
                              void* d_out, int out_size) {
    const float* x    = (const float*)d_in[0];
    const float* feat = (const float*)d_in[1];
    const float* z    = (const float*)d_in[2];
    const float* Wep1 = (const float*)d_in[3];
    const float* bep1 = (const float*)d_in[4];
    const float* Wep2 = (const float*)d_in[5];
    const float* bep2 = (const float*)d_in[6];
    const float* Wp1  = (const float*)d_in[7];
    const float* bp1  = (const float*)d_in[8];
    const float* Wp2  = (const float*)d_in[9];
    const float* bp2  = (const float*)d_in[10];
    const float* Wp3  = (const float*)d_in[11];
    const float* bp3  = (const float*)d_in[12];
    float* out = (float*)d_out;

    cudaFuncSetAttribute(gemm_mma, cudaFuncAttributeMaxDynamicSharedMemorySize,
                         NSTAGE * STAGE_B);

    convert_split_A<<<(B_DIM * KTOT / 4) / 256, 256>>>(x, feat);
    transpose_split_W<<<dim3(64, 16), dim3(32, 8)>>>(Wep1);
    repack_wp1<<<(STATE * PRI_N + 255) / 256, 256>>>(Wp1);
    gemm_mma<<<dim3(EPI_H / GM_BN, B_DIM / GM_BM), GM_THREADS, NSTAGE * STAGE_B>>>(bep1);
    sgemm_prior<<<dim3(PRI_N / P_BN, B_DIM / P_BM), 128>>>(x, bp1);
    epilogue_kernel<<<B_DIM / 8, 512>>>(z, Wep1, Wep2, bep2, Wp2, bp2, Wp3, bp3, out);
}